// round 17
// baseline (speedup 1.0000x reference)
#include <cuda_runtime.h>

#define NBANDS 31
#define NB     16
#define NT     1000
#define NF     257
#define NO     128
#define MAXC   34
#define KTOT   536      // sum of roundup4(2*bw)
#define KTOT4  540      // + 4 overread rows for clamp-free prefetch
#define TT     10       // time tile per block
#define YS     12       // y row stride (floats, 48B: keeps 16B alignment)
#define NCH    4        // stats chunks per (b,band)
#define OUTW   (NO * NBANDS)   // 3968
#define OHW    (64 * NBANDS)   // 1984 floats per (t, o-half)

__constant__ int c_bw[NBANDS] = {
    2,3,3,3,3,3,3,3,3,3,3,
    8,8,8,8,8,8,8,8,8,8,8,8,
    16,16,16,16,16,16,16,17
};
__constant__ int c_kal[NBANDS] = {
    0,4,12,20,28,36,44,52,60,68,76,
    84,100,116,132,148,164,180,196,212,228,244,260,
    276,308,340,372,404,436,468,500
};
// sentinel-terminated for slot->band scan
__constant__ int c_kalE[NBANDS + 1] = {
    0,4,12,20,28,36,44,52,60,68,76,
    84,100,116,132,148,164,180,196,212,228,244,260,
    276,308,340,372,404,436,468,500,536
};
__constant__ int c_f0[NBANDS] = {
    0,2,5,8,11,14,17,20,23,26,29,
    32,40,48,56,64,72,80,88,96,104,112,120,
    128,144,160,176,192,208,224,240
};
// 16 band-groups rebalanced by cost = kcnt + 3: max 44
__constant__ int c_gs[17] = {0,1,3,5,7,8,9,10,11,13,15,17,19,21,23,27,31};
__constant__ int c_gb[31] = {
    30,
    23,0,  24,1,  25,2,
    26, 27, 28, 29,
    11,12, 13,14, 15,16, 17,18, 19,20, 21,22,
    3,4,5,6,
    7,8,9,10
};

// static scratch
__device__ float  d_w2h[2 * KTOT4 * 64];      // per-half weights + overread rows
__device__ float  d_bp[NBANDS * NO];          // interleaved-o bias
__device__ float2 d_ps[NB * NBANDS * NCH];    // partial (sum, sumsq)

__device__ __forceinline__ int kg_of_f(int f)
{
    if (f >= 32) return 2 * f + 20;
    if (f >= 2)  return 2 * f - 2 + 2 * ((f + 1) / 3);
    return 2 * f;
}

__device__ __forceinline__ float2 u2f(unsigned long long u)
{
    float2 r;
    asm("mov.b64 {%0,%1}, %2;" : "=f"(r.x), "=f"(r.y) : "l"(u));
    return r;
}
__device__ __forceinline__ unsigned long long dupf(float f)
{
    unsigned long long r;
    asm("mov.b64 %0, {%1, %1};" : "=l"(r) : "f"(f));
    return r;
}

// ---------------------------------------------------------------------------
// Kernel A: z < NCH -> stats partial sums (predicated 4-way loads: MLP 4 even
//           for small-band chunks); z == NCH && b == 0 -> weight/bias prep.
// ---------------------------------------------------------------------------
__global__ __launch_bounds__(256)
void stats1_prep(const float* __restrict__ x,
                 const float* __restrict__ fcw, const float* __restrict__ fcb)
{
    const int b    = blockIdx.x;
    const int band = blockIdx.y;
    const int ch   = blockIdx.z;
    const int bw   = c_bw[band];
    const int kal  = c_kal[band];

    if (ch == NCH) {
        if (b != 0) return;
        const int C = 2 * bw;
        for (int idx = threadIdx.x; idx < C * NO; idx += 256) {
            const int k = idx >> 7;
            const int p = idx & 127;
            const int h = p >> 6;
            const int r = p & 63;
            const int l = r >> 1;
            const int s = r & 1;
            const int o = h * 64 + l + 32 * s;
            d_w2h[(h * KTOT4 + kal + k) * 64 + 2 * l + s] =
                fcw[(band * NO + o) * MAXC + k];
        }
        if (threadIdx.x < NO) {
            const int p = threadIdx.x;
            const int h = p >> 6;
            const int r = p & 63;
            const int l = r >> 1;
            const int s = r & 1;
            d_bp[band * NO + p] = fcb[band * NO + h * 64 + l + 32 * s];
        }
        return;
    }

    const float4* p = (const float4*)(x + (size_t)(b * NF + c_f0[band]) * (NT * 2));
    const int nv = bw * NT / 2;
    const int i0 = (int)((long long)nv * ch / NCH);
    const int i1 = (int)((long long)nv * (ch + 1) / NCH);

    const float4 z4 = make_float4(0.f, 0.f, 0.f, 0.f);
    float4 a1 = z4, a2 = z4;
    // predicated 4-way: 4 independent loads in flight even on short chunks
    for (int i = i0 + threadIdx.x; i < i1; i += 1024) {
        float4 v0 = p[i];
        float4 v1 = (i + 256 < i1) ? p[i + 256] : z4;
        float4 v2 = (i + 512 < i1) ? p[i + 512] : z4;
        float4 v3 = (i + 768 < i1) ? p[i + 768] : z4;
        a1.x += v0.x; a1.y += v0.y; a1.z += v0.z; a1.w += v0.w;
        a2.x = fmaf(v0.x, v0.x, a2.x); a2.y = fmaf(v0.y, v0.y, a2.y);
        a2.z = fmaf(v0.z, v0.z, a2.z); a2.w = fmaf(v0.w, v0.w, a2.w);
        a1.x += v1.x; a1.y += v1.y; a1.z += v1.z; a1.w += v1.w;
        a2.x = fmaf(v1.x, v1.x, a2.x); a2.y = fmaf(v1.y, v1.y, a2.y);
        a2.z = fmaf(v1.z, v1.z, a2.z); a2.w = fmaf(v1.w, v1.w, a2.w);
        a1.x += v2.x; a1.y += v2.y; a1.z += v2.z; a1.w += v2.w;
        a2.x = fmaf(v2.x, v2.x, a2.x); a2.y = fmaf(v2.y, v2.y, a2.y);
        a2.z = fmaf(v2.z, v2.z, a2.z); a2.w = fmaf(v2.w, v2.w, a2.w);
        a1.x += v3.x; a1.y += v3.y; a1.z += v3.z; a1.w += v3.w;
        a2.x = fmaf(v3.x, v3.x, a2.x); a2.y = fmaf(v3.y, v3.y, a2.y);
        a2.z = fmaf(v3.z, v3.z, a2.z); a2.w = fmaf(v3.w, v3.w, a2.w);
    }
    float s  = (a1.x + a1.y) + (a1.z + a1.w);
    float s2 = (a2.x + a2.y) + (a2.z + a2.w);
    for (int off = 16; off; off >>= 1) {
        s  += __shfl_down_sync(0xFFFFFFFFu, s,  off);
        s2 += __shfl_down_sync(0xFFFFFFFFu, s2, off);
    }
    __shared__ float sh0[8], sh1[8];
    const int w = threadIdx.x >> 5, l = threadIdx.x & 31;
    if (l == 0) { sh0[w] = s; sh1[w] = s2; }
    __syncthreads();
    if (threadIdx.x == 0) {
        float ts = 0.f, ts2 = 0.f;
        #pragma unroll
        for (int k = 0; k < 8; k++) { ts += sh0[k]; ts2 += sh1[k]; }
        d_ps[(b * NBANDS + band) * NCH + ch] = make_float2(ts, ts2);
    }
}

// ---------------------------------------------------------------------------
// Fused kernel: stats finalize folded into the prologue (fp32 combine —
// rel_err headroom is 4 orders of magnitude). Exact k-count, clamp-free
// depth-4 weight pipeline, t-pair f32x2, conflict-free staging, bulk stores.
// ---------------------------------------------------------------------------
#define SOUT_F   (TT * OHW)                   // 19840 floats (79360 B)
#define SY_F     (KTOT * YS)                  // 6432 floats  (25728 B)
#define SMEM_F   (SOUT_F + SY_F + 2 * KTOT + 2 * NBANDS)  // 109624 B

#define FMA2(acc, wv, yv) \
    asm("fma.rn.f32x2 %0, %1, %2, %0;" : "+l"(acc) : "l"(wv), "l"(yv));

__global__ __launch_bounds__(512, 2)
void fused_kernel(const float* __restrict__ x,
                  const float* __restrict__ gnw,
                  const float* __restrict__ gnb,
                  float* __restrict__ out)
{
    extern __shared__ float sm[];
    float* s_out  = sm;                       // [t][OHW] exact output order
    float* s_y    = sm + SOUT_F;              // [k][YS] (10 valid floats/row)
    float* s_A    = sm + SOUT_F + SY_F;
    float* s_B    = s_A + KTOT;
    float* s_mean = s_B + KTOT;               // [NBANDS]
    float* s_inv  = s_mean + NBANDS;

    const int b    = blockIdx.y;
    const int t0   = blockIdx.x * TT;
    const int h    = blockIdx.z;              // o-half
    const int tid  = threadIdx.x;
    const int lane = tid & 31;
    const int warp = tid >> 5;                // band group

    const unsigned long long* wbase =
        (const unsigned long long*)d_w2h + (size_t)h * KTOT4 * 32;

    // --- prefetch first band's bias + first 4 weight rows (hidden by prologue)
    int bi          = c_gs[warp];
    const int biEnd = c_gs[warp + 1];
    int band = c_gb[bi];
    int kal  = c_kal[band];
    unsigned long long bz =
        *((const unsigned long long*)(d_bp + band * NO + h * 64) + lane);
    const unsigned long long* wp = wbase + kal * 32 + lane;
    unsigned long long wq0 = wp[0];
    unsigned long long wq1 = wp[32];
    unsigned long long wq2 = wp[64];
    unsigned long long wq3 = wp[96];

    // stats finalize (fp32): per-band mean/inv from the NCH partials
    if (tid < NBANDS) {
        float ts = 0.f, ts2 = 0.f;
        #pragma unroll
        for (int i = 0; i < NCH; i++) {
            float2 v = d_ps[(b * NBANDS + tid) * NCH + i];
            ts += v.x; ts2 += v.y;
        }
        const float n    = 2000.0f * (float)c_bw[tid];
        const float mean = ts / n;
        const float var  = ts2 / n - mean * mean;
        s_mean[tid] = mean;
        s_inv[tid]  = rsqrtf(var + 1e-5f);
    }
    __syncthreads();

    // build A,B: slot -> band by short scan, fold GN affine
    for (int i = tid; i < KTOT; i += 512) {
        int bd = 0;
        while (i >= c_kalE[bd + 1]) bd++;
        const int j = i - c_kalE[bd];
        const float A = gnw[bd * MAXC + j] * s_inv[bd];
        s_A[i] = A;
        s_B[i] = gnb[bd * MAXC + j] - A * s_mean[bd];
    }
    __syncthreads();

    // y-build: s_y[kg][t] = A*x + B; float4 covers (t,t+1)x(re,im) -> 2 STS.64
    for (int idx = tid; idx < NF * 5; idx += 512) {
        const int f = idx / 5;
        const int q = idx - 5 * f;            // t-pair q: t = t0+2q, t0+2q+1
        const float4 v = *(const float4*)(x + ((size_t)(b * NF + f) * NT + t0) * 2 + q * 4);
        const int kg = kg_of_f(f);
        const float A0 = s_A[kg], B0 = s_B[kg];
        const float A1 = s_A[kg + 1], B1 = s_B[kg + 1];
        *(float2*)&s_y[kg * YS + 2 * q] =
            make_float2(fmaf(A0, v.x, B0), fmaf(A0, v.z, B0));
        *(float2*)&s_y[(kg + 1) * YS + 2 * q] =
            make_float2(fmaf(A1, v.y, B1), fmaf(A1, v.w, B1));
    }
    __syncthreads();

    // --- band loop, exact k-count, clamp-free depth-4 weight pipeline
    for (;;) {
        const int kcnt = 2 * c_bw[band];      // exact (even), no pad iters
        const float* yb = s_y + kal * YS;

        unsigned long long acc[5][2];   // [t-pair][oA/oB]
        {
            float2 bf = u2f(bz);
            unsigned long long bA = dupf(bf.x), bB = dupf(bf.y);
            #pragma unroll
            for (int tp = 0; tp < 5; tp++) { acc[tp][0] = bA; acc[tp][1] = bB; }
        }

        #pragma unroll 4
        for (int k = 0; k < kcnt; k++) {
            const unsigned long long w = wq0;
            wq0 = wq1; wq1 = wq2; wq2 = wq3;
            wq3 = wp[(k + 4) * 32];           // overread OK (4 spare rows)

            float2 wf = u2f(w);
            const unsigned long long wA = dupf(wf.x);
            const unsigned long long wB = dupf(wf.y);

            const ulonglong2 y01 = *(const ulonglong2*)(yb + k * YS);      // pairs 0,1
            const ulonglong2 y23 = *(const ulonglong2*)(yb + k * YS + 4);  // pairs 2,3
            const unsigned long long y4 =
                *(const unsigned long long*)(yb + k * YS + 8);             // pair 4
            FMA2(acc[0][0], wA, y01.x) FMA2(acc[0][1], wB, y01.x)
            FMA2(acc[1][0], wA, y01.y) FMA2(acc[1][1], wB, y01.y)
            FMA2(acc[2][0], wA, y23.x) FMA2(acc[2][1], wB, y23.x)
            FMA2(acc[3][0], wA, y23.y) FMA2(acc[3][1], wB, y23.y)
            FMA2(acc[4][0], wA, y4)    FMA2(acc[4][1], wB, y4)
        }

        // prefetch next band before staging stores
        const int curBand = band;
        const bool more = (++bi < biEnd);
        if (more) {
            band = c_gb[bi];
            kal  = c_kal[band];
            wp   = wbase + kal * 32 + lane;
            bz   = *((const unsigned long long*)(d_bp + band * NO + h * 64) + lane);
            wq0 = wp[0]; wq1 = wp[32]; wq2 = wp[64]; wq3 = wp[96];
        }

        // conflict-free staging: addr = 31*lane + band (+992 for o+32)
        #pragma unroll
        for (int tp = 0; tp < 5; tp++) {
            float* so = s_out + (2 * tp) * OHW + 31 * lane + curBand;
            float2 pa = u2f(acc[tp][0]);    // o = h*64 + lane,    t / t+1
            float2 pb = u2f(acc[tp][1]);    // o = h*64 + lane+32
            so[0]         = pa.x;
            so[OHW]       = pa.y;
            so[992]       = pb.x;
            so[OHW + 992] = pb.y;
        }
        if (!more) break;
    }
    __syncthreads();

    // per-t contiguous bulk copies: 7936 B each (o-half slab is contiguous)
    if (tid == 0) {
        unsigned int saddr;
        asm("{ .reg .u64 t; cvta.to.shared.u64 t, %1; cvt.u32.u64 %0, t; }"
            : "=r"(saddr) : "l"(s_out));
        asm volatile("fence.proxy.async.shared::cta;" ::: "memory");
        #pragma unroll
        for (int t = 0; t < TT; t++) {
            float* dst = out + (size_t)(b * NT + t0 + t) * OUTW + h * OHW;
            asm volatile("cp.async.bulk.global.shared::cta.bulk_group [%0], [%1], %2;"
                         :: "l"(dst), "r"(saddr + t * (OHW * 4)), "n"(OHW * 4)
                         : "memory");
        }
        asm volatile("cp.async.bulk.commit_group;" ::: "memory");
        asm volatile("cp.async.bulk.wait_group.read 0;" ::: "memory");
    }
}

// ---------------------------------------------------------------------------
extern "C" void kernel_launch(void* const* d_in, const int* in_sizes, int n_in,
                              void* d_out, int out_size)
{
    const float* x   = (const float*)d_in[0];
    const float* gnw = (const float*)d_in[1];
    const float* gnb = (const float*)d_in[2];
    const float* fcw = (const float*)d_in[3];
    const float* fcb = (const float*)d_in[4];
    float* out = (float*)d_out;

    const int smem_bytes = SMEM_F * 4;        // 109624 B -> occ 2
    cudaFuncSetAttribute(fused_kernel,
                         cudaFuncAttributeMaxDynamicSharedMemorySize, smem_bytes);

    stats1_prep<<<dim3(NB, NBANDS, NCH + 1), 256>>>(x, fcw, fcb);
    fused_kernel<<<dim3(NT / TT, NB, 2), 512, smem_bytes>>>(x, gnw, gnb, out);
}